// round 2
// baseline (speedup 1.0000x reference)
#include <cuda_runtime.h>

// EEG_SimpleLSM: 3-layer LIF winner-take-all liquid state machine.
// x: [256, 32, 4000] f32, W1: [64,32], W2: [128,64]. Output: exp(pre_v2@T-1) [256,128].
//
// Spikes are one-hot (WTA) -> s@W.T is a single-column gather.
// One warp per sample, 2 samples per CTA (64 threads) so each warp owns its
// own SMSP on its own SM (128 CTAs < 148 SMs) -- round 1 showed single-warp
// CTAs doubling up on SMSP0.
// Argmax: monotone-int key + REDUX.UMAX, then BALLOT(key==max)+FFS for the
// first-index tie-break (replaces a second REDUX; vote is cheaper and the
// layer-1 pairwise tie-break ballot issues in parallel with the REDUX).
// Division by constant tau via Markstein mul+2fma (correctly rounded,
// independent of fast-math flags) to track the reference trajectory exactly.

#define NB   256
#define NCH  32
#define NT   4000

__device__ __align__(16) float g_W1T[32 * 64];   // W1T[c][j] = W1[j][c]
__device__ __align__(16) float g_W2T[64 * 128];  // W2T[c][j] = W2[j][c]

__global__ void prep_kernel(const float* __restrict__ W1, const float* __restrict__ W2) {
    int tid = blockIdx.x * blockDim.x + threadIdx.x;
    int nthr = blockDim.x * gridDim.x;
    for (int i = tid; i < 64 * 32; i += nthr) {
        int r = i >> 5, c = i & 31;
        g_W1T[c * 64 + r] = W1[i];
    }
    for (int i = tid; i < 128 * 64; i += nthr) {
        int r = i >> 6, c = i & 63;
        g_W2T[c * 128 + r] = W2[i];
    }
}

// Correctly-rounded division by constant c (rc = RN(1/c)), Markstein sequence.
__device__ __forceinline__ float divc(float v, float c, float rc) {
    float q = v * rc;
    float r = __fmaf_rn(-c, q, v);
    return __fmaf_rn(r, rc, q);
}

// Monotone key: strictly order-preserving float -> unsigned mapping.
__device__ __forceinline__ unsigned fkey(float v) {
    unsigned b = __float_as_uint(v);
    return b ^ ((unsigned)((int)b >> 31) | 0x80000000u);
}

// key(1.5f): bits 0x3FC00000 -> 0xBFC00000 ; key(1.2f): 0x3F99999A -> 0xBF99999A
#define KEY_VTH0 0xBFC00000u
#define KEY_VTH1 0xBF99999Au

__global__ void __launch_bounds__(64)
lsm_kernel(const float* __restrict__ x, float* __restrict__ out) {
    const int warp = threadIdx.x >> 5;
    const int b    = blockIdx.x * 2 + warp;
    const int lane = threadIdx.x & 31;

    const float RC3 = 1.0f / 3.0f;
    const float RCT = 1.0f / 80000.0f;

    // Per-lane state: lane l owns v0[l], v1[2l..2l+1], v2[4l..4l+3]
    float v0  = 0.0f;
    float v1a = 0.0f, v1b = 0.0f;
    float4 v2 = make_float4(0.f, 0.f, 0.f, 0.f);
    float4 pc = make_float4(0.f, 0.f, 0.f, 0.f);  // last charged (pre-reset) v2

    // x[b, lane, :] contiguous in t. 8 steps (32B sector) per lane per block.
    const float4* xp = reinterpret_cast<const float4*>(x + (size_t)b * (NCH * NT) + lane * NT);

    float4 c0 = __ldg(xp + 0);
    float4 c1 = __ldg(xp + 1);

    const float2* w1p = reinterpret_cast<const float2*>(g_W1T);
    const float4* w2p = reinterpret_cast<const float4*>(g_W2T);

    const int NBLK = NT / 8;  // 500
    for (int blk = 0; blk < NBLK; ++blk) {
        int nb = (blk + 1 < NBLK) ? (blk + 1) * 2 : 0;
        float4 n0 = __ldg(xp + nb);
        float4 n1 = __ldg(xp + nb + 1);

        float xs[8] = {c0.x, c0.y, c0.z, c0.w, c1.x, c1.y, c1.z, c1.w};

#pragma unroll
        for (int j = 0; j < 8; ++j) {
            // ---- layer 0: charge v0 = (v0 + x) - v0/3 ----
            float d0 = divc(v0, 3.0f, RC3);
            float ch0 = (v0 + xs[j]) - d0;

            // WTA argmax over 32 lanes: redux max + ballot/ffs first-index
            unsigned k0 = fkey(ch0);
            unsigned m0 = __reduce_max_sync(0xFFFFFFFFu, k0);
            unsigned bal0 = __ballot_sync(0xFFFFFFFFu, k0 == m0);
            unsigned idx0 = (unsigned)__ffs(bal0) - 1u;
            float s0 = (m0 >= KEY_VTH0) ? 1.0f : 0.0f;

            // hard reset (unmasked spike), v_reset = 0
            v0 = (ch0 >= 1.5f) ? 0.0f : ch0;

            // ---- layer 1: h1 = s0 * W1[:, idx0]; v1 = (v1 + h1) - v1/80000 ----
            float2 w1 = __ldg(w1p + (idx0 << 5) + lane);  // W1T[idx0][2l..2l+1]
            float d1a = divc(v1a, 80000.0f, RCT);
            float d1b = divc(v1b, 80000.0f, RCT);
            float cha = __fmaf_rn(w1.x, s0, v1a) - d1a;   // exact: s0 in {0,1}
            float chb = __fmaf_rn(w1.y, s0, v1b) - d1b;

            // WTA argmax over 64 (2 per lane, first-index tie-break).
            // bwbits ballot is independent of the REDUX -> issues in parallel.
            unsigned ka = fkey(cha);
            unsigned kb = fkey(chb);
            unsigned bwbits = __ballot_sync(0xFFFFFFFFu, kb > ka);
            unsigned lk = (kb > ka) ? kb : ka;
            unsigned m1 = __reduce_max_sync(0xFFFFFFFFu, lk);
            unsigned bal1 = __ballot_sync(0xFFFFFFFFu, lk == m1);
            unsigned wl = (unsigned)__ffs(bal1) - 1u;
            unsigned idx1 = 2u * wl + ((bwbits >> wl) & 1u);
            float s1 = (m1 >= KEY_VTH1) ? 1.0f : 0.0f;

            v1a = (cha >= 1.2f) ? 0.0f : cha;
            v1b = (chb >= 1.2f) ? 0.0f : chb;

            // ---- layer 2: h2 = s1 * W2[:, idx1]; charge; keep pre-reset ----
            float4 w2 = __ldg(w2p + (idx1 << 5) + lane);  // W2T[idx1][4l..4l+3]
            float4 d2;
            d2.x = divc(v2.x, 80000.0f, RCT);
            d2.y = divc(v2.y, 80000.0f, RCT);
            d2.z = divc(v2.z, 80000.0f, RCT);
            d2.w = divc(v2.w, 80000.0f, RCT);
            pc.x = __fmaf_rn(w2.x, s1, v2.x) - d2.x;
            pc.y = __fmaf_rn(w2.y, s1, v2.y) - d2.y;
            pc.z = __fmaf_rn(w2.z, s1, v2.z) - d2.z;
            pc.w = __fmaf_rn(w2.w, s1, v2.w) - d2.w;
            v2.x = (pc.x >= 1.2f) ? 0.0f : pc.x;
            v2.y = (pc.y >= 1.2f) ? 0.0f : pc.y;
            v2.z = (pc.z >= 1.2f) ? 0.0f : pc.z;
            v2.w = (pc.w >= 1.2f) ? 0.0f : pc.w;
        }

        c0 = n0;
        c1 = n1;
    }

    // liquid state: exp of last-step pre-reset v2
    float4 o;
    o.x = expf(pc.x);
    o.y = expf(pc.y);
    o.z = expf(pc.z);
    o.w = expf(pc.w);
    reinterpret_cast<float4*>(out + (size_t)b * 128)[lane] = o;
}

extern "C" void kernel_launch(void* const* d_in, const int* in_sizes, int n_in,
                              void* d_out, int out_size) {
    const float* x  = (const float*)d_in[0];
    const float* W1 = (const float*)d_in[1];
    const float* W2 = (const float*)d_in[2];
    float* out = (float*)d_out;

    prep_kernel<<<1, 256>>>(W1, W2);
    lsm_kernel<<<NB / 2, 64>>>(x, out);
}

// round 3
// speedup vs baseline: 1.5709x; 1.5709x over previous
#include <cuda_runtime.h>

// EEG_SimpleLSM: 3-layer LIF winner-take-all liquid state machine.
// x: [256, 32, 4000] f32, W1: [64,32], W2: [128,64]. Output: exp(pre_v2@T-1) [256,128].
//
// Spikes are one-hot (WTA) -> s@W.T is a single-column gather.
// One warp per sample. Lane l owns v0[l], v1[2l..2l+1], v2[4l..4l+3].
//
// ROUND 3: software-pipelined across layers. Layer 0 at step t+2 is
// independent of layers 1/2 at steps t+1/t, so each loop iteration runs
//   L2(t)   consuming the (s1,idx1) token produced last iteration,
//   L1(t+1) consuming the (s0,idx0) token produced last iteration,
//   L0(t+2) producing a fresh (s0,idx0) token.
// The three REDUX chains + two gathers overlap; exposed recurrences are only
// the short per-layer v updates. Warm-up is implicit: with all state zero and
// zero tokens, dummy L1/L2 steps are exact no-ops that emit zero tokens.
//
// Numerics identical to the sequential version (pure reordering):
// Markstein mul+2fma constant division (correctly rounded regardless of
// fast-math), fma gathers with s in {0,1} (exact), REDUX max on monotone int
// keys + REDUX min on candidate indices (first-index tie-break, needed
// because all-zero membranes tie in early steps).

#define NB   256
#define NCH  32
#define NT   4000

__device__ __align__(16) float g_W1T[32 * 64];   // W1T[c][j] = W1[j][c]
__device__ __align__(16) float g_W2T[64 * 128];  // W2T[c][j] = W2[j][c]

__global__ void prep_kernel(const float* __restrict__ W1, const float* __restrict__ W2) {
    int tid = blockIdx.x * blockDim.x + threadIdx.x;
    int nthr = blockDim.x * gridDim.x;
    for (int i = tid; i < 64 * 32; i += nthr) {
        int r = i >> 5, c = i & 31;
        g_W1T[c * 64 + r] = W1[i];
    }
    for (int i = tid; i < 128 * 64; i += nthr) {
        int r = i >> 6, c = i & 63;
        g_W2T[c * 128 + r] = W2[i];
    }
}

// Correctly-rounded division by constant c (rc = RN(1/c)), Markstein sequence.
__device__ __forceinline__ float divc(float v, float c, float rc) {
    float q = v * rc;
    float r = __fmaf_rn(-c, q, v);
    return __fmaf_rn(r, rc, q);
}

// Monotone key: strictly order-preserving float -> unsigned mapping.
__device__ __forceinline__ unsigned fkey(float v) {
    unsigned b = __float_as_uint(v);
    return b ^ ((unsigned)((int)b >> 31) | 0x80000000u);
}

// key(1.5f): 0x3FC00000 -> 0xBFC00000 ; key(1.2f): 0x3F99999A -> 0xBF99999A
#define KEY_VTH0 0xBFC00000u
#define KEY_VTH1 0xBF99999Au

// ---- pipeline stages ----

__device__ __forceinline__ void stage0(float xv, int lane, float& v0,
                                       float& s0_out, unsigned& idx0_out) {
    float d0  = divc(v0, 3.0f, 1.0f / 3.0f);
    float ch0 = (v0 + xv) - d0;
    unsigned k0   = fkey(ch0);
    unsigned m0   = __reduce_max_sync(0xFFFFFFFFu, k0);
    unsigned cand = (k0 == m0) ? (unsigned)lane : 32u;
    idx0_out = __reduce_min_sync(0xFFFFFFFFu, cand);
    s0_out   = (m0 >= KEY_VTH0) ? 1.0f : 0.0f;
    v0 = (ch0 >= 1.5f) ? 0.0f : ch0;
}

__device__ __forceinline__ void stage1(const float2* __restrict__ w1p, int lane,
                                       unsigned idx0, float s0,
                                       float& v1a, float& v1b,
                                       float& s1_out, unsigned& idx1_out) {
    const float RCT = 1.0f / 80000.0f;
    float2 w1 = __ldg(w1p + (idx0 << 5) + lane);   // W1T[idx0][2l..2l+1]
    float d1a = divc(v1a, 80000.0f, RCT);
    float d1b = divc(v1b, 80000.0f, RCT);
    float cha = __fmaf_rn(w1.x, s0, v1a) - d1a;    // exact: s0 in {0,1}
    float chb = __fmaf_rn(w1.y, s0, v1b) - d1b;
    unsigned ka = fkey(cha);
    unsigned kb = fkey(chb);
    bool bw = kb > ka;
    unsigned lk = bw ? kb : ka;
    unsigned li = 2u * (unsigned)lane + (bw ? 1u : 0u);
    unsigned m1   = __reduce_max_sync(0xFFFFFFFFu, lk);
    unsigned cand = (lk == m1) ? li : 64u;
    idx1_out = __reduce_min_sync(0xFFFFFFFFu, cand);
    s1_out   = (m1 >= KEY_VTH1) ? 1.0f : 0.0f;
    v1a = (cha >= 1.2f) ? 0.0f : cha;
    v1b = (chb >= 1.2f) ? 0.0f : chb;
}

__device__ __forceinline__ void stage2(const float4* __restrict__ w2p, int lane,
                                       unsigned idx1, float s1,
                                       float4& v2, float4& pc) {
    const float RCT = 1.0f / 80000.0f;
    float4 w2 = __ldg(w2p + (idx1 << 5) + lane);   // W2T[idx1][4l..4l+3]
    float dx = divc(v2.x, 80000.0f, RCT);
    float dy = divc(v2.y, 80000.0f, RCT);
    float dz = divc(v2.z, 80000.0f, RCT);
    float dw = divc(v2.w, 80000.0f, RCT);
    pc.x = __fmaf_rn(w2.x, s1, v2.x) - dx;
    pc.y = __fmaf_rn(w2.y, s1, v2.y) - dy;
    pc.z = __fmaf_rn(w2.z, s1, v2.z) - dz;
    pc.w = __fmaf_rn(w2.w, s1, v2.w) - dw;
    v2.x = (pc.x >= 1.2f) ? 0.0f : pc.x;
    v2.y = (pc.y >= 1.2f) ? 0.0f : pc.y;
    v2.z = (pc.z >= 1.2f) ? 0.0f : pc.z;
    v2.w = (pc.w >= 1.2f) ? 0.0f : pc.w;
}

__global__ void __launch_bounds__(32)
lsm_kernel(const float* __restrict__ x, float* __restrict__ out) {
    const int b    = blockIdx.x;
    const int lane = threadIdx.x;

    // Per-lane state
    float v0  = 0.0f;
    float v1a = 0.0f, v1b = 0.0f;
    float4 v2 = make_float4(0.f, 0.f, 0.f, 0.f);
    float4 pc = make_float4(0.f, 0.f, 0.f, 0.f);

    // Pipeline tokens. Zero tokens make the first one/two L1/L2 executions
    // exact no-ops on all-zero state (they emit zero tokens themselves).
    float    s0_d = 0.0f;  unsigned idx0_d = 0u;
    float    s1_d = 0.0f;  unsigned idx1_d = 0u;

    const float4* xp = reinterpret_cast<const float4*>(x + (size_t)b * (NCH * NT) + lane * NT);
    const float2* w1p = reinterpret_cast<const float2*>(g_W1T);
    const float4* w2p = reinterpret_cast<const float4*>(g_W2T);

    float4 c0 = __ldg(xp + 0);
    float4 c1 = __ldg(xp + 1);

    const int NBLK = NT / 8;  // 500
    for (int blk = 0; blk < NBLK; ++blk) {
        int nb = (blk + 1 < NBLK) ? (blk + 1) * 2 : 0;
        float4 n0 = __ldg(xp + nb);
        float4 n1 = __ldg(xp + nb + 1);

        float xs[8] = {c0.x, c0.y, c0.z, c0.w, c1.x, c1.y, c1.z, c1.w};

#pragma unroll
        for (int j = 0; j < 8; ++j) {
            // L2 lags 2 steps, L1 lags 1 step, L0 is current. All three are
            // mutually independent within this iteration -> full overlap.
            stage2(w2p, lane, idx1_d, s1_d, v2, pc);
            stage1(w1p, lane, idx0_d, s0_d, v1a, v1b, s1_d, idx1_d);
            stage0(xs[j], lane, v0, s0_d, idx0_d);
        }

        c0 = n0;
        c1 = n1;
    }

    // Drain the pipeline: L2(T-2), L1(T-1), L2(T-1).
    stage2(w2p, lane, idx1_d, s1_d, v2, pc);
    stage1(w1p, lane, idx0_d, s0_d, v1a, v1b, s1_d, idx1_d);
    stage2(w2p, lane, idx1_d, s1_d, v2, pc);

    // liquid state: exp of last-step pre-reset v2
    float4 o;
    o.x = expf(pc.x);
    o.y = expf(pc.y);
    o.z = expf(pc.z);
    o.w = expf(pc.w);
    reinterpret_cast<float4*>(out + (size_t)b * 128)[lane] = o;
}

extern "C" void kernel_launch(void* const* d_in, const int* in_sizes, int n_in,
                              void* d_out, int out_size) {
    const float* x  = (const float*)d_in[0];
    const float* W1 = (const float*)d_in[1];
    const float* W2 = (const float*)d_in[2];
    float* out = (float*)d_out;

    prep_kernel<<<1, 256>>>(W1, W2);
    lsm_kernel<<<NB, 32>>>(x, out);
}